// round 15
// baseline (speedup 1.0000x reference)
#include <cuda_runtime.h>

#define Bb 2
#define Ss 2048
#define Dd 512
#define Hh 8
#define DHh 64
#define CAPS 256     // total candidate cap per row (two 128-entry halves)
#define HCAP 128     // per-half cap

// Scratch (device globals: no runtime allocation allowed)
__device__ float          g_Q[Bb * Hh * Ss * DHh];       // [B,H,S,dh]  8 MB
__device__ float          g_K[Bb * Hh * Ss * DHh];       // [B,H,S,dh]  8 MB
__device__ float          g_V[Bb * Ss * DHh];            // [B,S,dh]    1 MB
__device__ float          g_heads[Bb * Ss * Dd];         // [B,S,D]     8 MB
__device__ unsigned short g_cand[Bb * Hh * Ss * CAPS];   // cand indices (2 halves)
__device__ int            g_ccnt[Bb * Hh * Ss * 2];      // per-half counts
__device__ unsigned       g_rmaxU[Bb * Hh * Ss];         // encoded row maxes

__device__ __forceinline__ unsigned enc_f(float f) {
    unsigned b = __float_as_uint(f);
    return (f >= 0.0f) ? (b | 0x80000000u) : ~b;
}
__device__ __forceinline__ float dec_f(unsigned u) {
    return (u & 0x80000000u) ? __uint_as_float(u & 0x7fffffffu)
                             : __uint_as_float(~u);
}
__device__ __forceinline__ unsigned f2tf32(float f) {
    unsigned u;
    asm("cvt.rna.tf32.f32 %0, %1;" : "=r"(u) : "f"(f));
    return u;
}

#define MMA3(d, a, b) asm volatile( \
    "mma.sync.aligned.m16n8k8.row.col.f32.tf32.tf32.f32 " \
    "{%0,%1,%2,%3}, {%4,%5,%6,%7}, {%8,%9}, {%0,%1,%2,%3};" \
    : "+f"(d[0]), "+f"(d[1]), "+f"(d[2]), "+f"(d[3]) \
    : "r"(a[0]), "r"(a[1]), "r"(a[2]), "r"(a[3]), "r"(b[0]), "r"(b[1]))

// ---------------------------------------------------------------------------
// 3xTF32 GEMM core (validated R11): C[128x64] = A(MxK)@W(KxN)+bias, K=512
// ---------------------------------------------------------------------------
#define G3_SMEM ((2 * 128 * 36 + 2 * 64 * 36) * 4)   // 55296 B

__device__ __forceinline__ void gemm3t_tile(
    const float* __restrict__ A, int lda,
    const float* __restrict__ W, int ldw,
    const float* __restrict__ bias,
    float* __restrict__ C,
    int m0, int n0, int ldc, int headMajor,
    unsigned* Ah, unsigned* Al, unsigned* Bh, unsigned* Bl)
{
    int tid = threadIdx.x;
    int wid = tid >> 5, lane = tid & 31;
    int wm = wid & 3, wn = wid >> 2;
    int g = lane >> 2, tg = lane & 3;

    float acc[2][4][4];
#pragma unroll
    for (int mt = 0; mt < 2; ++mt)
#pragma unroll
        for (int nt = 0; nt < 4; ++nt)
#pragma unroll
            for (int e = 0; e < 4; ++e) acc[mt][nt][e] = 0.0f;

    int arow = tid >> 1;
    int acb = (tid & 1) * 16;
    int bn = tid & 63;
    int bkb = (tid >> 6) * 8;

    for (int k0 = 0; k0 < Dd; k0 += 32) {
#pragma unroll
        for (int p = 0; p < 4; ++p) {
            int c = acb + p * 4;
            float4 v = *(const float4*)(A + (long)(m0 + arow) * lda + k0 + c);
            float vv[4] = {v.x, v.y, v.z, v.w};
#pragma unroll
            for (int u = 0; u < 4; ++u) {
                unsigned hi = f2tf32(vv[u]);
                Ah[arow * 36 + c + u] = hi;
                Al[arow * 36 + c + u] = f2tf32(vv[u] - __uint_as_float(hi));
            }
        }
#pragma unroll
        for (int u = 0; u < 8; ++u) {
            float v = W[(long)(k0 + bkb + u) * ldw + n0 + bn];
            unsigned hi = f2tf32(v);
            Bh[bn * 36 + bkb + u] = hi;
            Bl[bn * 36 + bkb + u] = f2tf32(v - __uint_as_float(hi));
        }
        __syncthreads();

#pragma unroll
        for (int kc = 0; kc < 32; kc += 8) {
            unsigned ah[2][4], al[2][4], bh[4][2], bl[4][2];
#pragma unroll
            for (int mt = 0; mt < 2; ++mt) {
                int r = wm * 32 + mt * 16 + g;
                ah[mt][0] = Ah[r * 36 + kc + tg];
                ah[mt][1] = Ah[(r + 8) * 36 + kc + tg];
                ah[mt][2] = Ah[r * 36 + kc + tg + 4];
                ah[mt][3] = Ah[(r + 8) * 36 + kc + tg + 4];
                al[mt][0] = Al[r * 36 + kc + tg];
                al[mt][1] = Al[(r + 8) * 36 + kc + tg];
                al[mt][2] = Al[r * 36 + kc + tg + 4];
                al[mt][3] = Al[(r + 8) * 36 + kc + tg + 4];
            }
#pragma unroll
            for (int nt = 0; nt < 4; ++nt) {
                int n = wn * 32 + nt * 8 + g;
                bh[nt][0] = Bh[n * 36 + kc + tg];
                bh[nt][1] = Bh[n * 36 + kc + tg + 4];
                bl[nt][0] = Bl[n * 36 + kc + tg];
                bl[nt][1] = Bl[n * 36 + kc + tg + 4];
            }
#pragma unroll
            for (int mt = 0; mt < 2; ++mt)
#pragma unroll
                for (int nt = 0; nt < 4; ++nt) {
                    MMA3(acc[mt][nt], ah[mt], bl[nt]);
                    MMA3(acc[mt][nt], al[mt], bh[nt]);
                    MMA3(acc[mt][nt], ah[mt], bh[nt]);
                }
        }
        __syncthreads();
    }

    int cb = wn * 32 + tg * 2;
#pragma unroll
    for (int mt = 0; mt < 2; ++mt) {
#pragma unroll
        for (int nt = 0; nt < 4; ++nt) {
            int r0 = m0 + wm * 32 + mt * 16 + g;
            int c = cb + nt * 8;
            float2 b2 = *(const float2*)(bias + n0 + c);
            float o0 = acc[mt][nt][0] + b2.x;
            float o1 = acc[mt][nt][1] + b2.y;
            float o2 = acc[mt][nt][2] + b2.x;
            float o3 = acc[mt][nt][3] + b2.y;
            if (headMajor) {
                int hh = n0 >> 6;
                int bb0 = r0 >> 11, ss0 = r0 & 2047;
                *(float2*)(C + ((((long)bb0 * Hh + hh) * Ss) + ss0) * DHh + c) =
                    make_float2(o0, o1);
                int r1 = r0 + 8;
                int bb1 = r1 >> 11, ss1 = r1 & 2047;
                *(float2*)(C + ((((long)bb1 * Hh + hh) * Ss) + ss1) * DHh + c) =
                    make_float2(o2, o3);
            } else {
                *(float2*)(C + (long)r0 * ldc + n0 + c) = make_float2(o0, o1);
                *(float2*)(C + (long)(r0 + 8) * ldc + n0 + c) = make_float2(o2, o3);
            }
        }
    }
}

__global__ __launch_bounds__(256) void proj3t(
    const float* __restrict__ x,
    const float* __restrict__ Wq, const float* __restrict__ bq,
    const float* __restrict__ Wk, const float* __restrict__ bk,
    const float* __restrict__ Wv, const float* __restrict__ bv,
    float* __restrict__ Qo, float* __restrict__ Ko, float* __restrict__ Vo)
{
    extern __shared__ unsigned sm3[];
    unsigned* Ah = sm3;
    unsigned* Al = sm3 + 128 * 36;
    unsigned* Bh = sm3 + 2 * 128 * 36;
    unsigned* Bl = Bh + 64 * 36;

    int y = blockIdx.y;
    int m0 = blockIdx.x * 128;
    if (y < 8)
        gemm3t_tile(x, Dd, Wq, Dd, bq, Qo, m0, y * 64, 0, 1, Ah, Al, Bh, Bl);
    else if (y < 16)
        gemm3t_tile(x, Dd, Wk, Dd, bk, Ko, m0, (y - 8) * 64, 0, 1, Ah, Al, Bh, Bl);
    else
        gemm3t_tile(x, Dd, Wv, DHh, bv, Vo, m0, 0, DHh, 0, Ah, Al, Bh, Bl);
}

__global__ __launch_bounds__(256) void wout3t(
    const float* __restrict__ A, const float* __restrict__ W,
    const float* __restrict__ bias, float* __restrict__ C)
{
    extern __shared__ unsigned sm3[];
    unsigned* Ah = sm3;
    unsigned* Al = sm3 + 128 * 36;
    unsigned* Bh = sm3 + 2 * 128 * 36;
    unsigned* Bl = Bh + 64 * 36;
    gemm3t_tile(A, Dd, W, Dd, bias, C,
                blockIdx.x * 128, blockIdx.y * 64, Dd, 0, Ah, Al, Bh, Bl);
}

// ---------------------------------------------------------------------------
// QK screening, K-half parallel (grid 2 x 16 x 16 = 512 CTAs per kernel).
// ---------------------------------------------------------------------------
#define QK_LDS 68
#define RMX_SMEM (2 * 128 * QK_LDS * 4 + 128 * 4)
#define SCR_SMEM (2 * 128 * QK_LDS * 4 + 128 * 4 + 128 * 4)

__device__ __forceinline__ void tile_mma(
    const unsigned* Qs, const unsigned* Ks,
    int wm, int wn, int g, int tg, float acc[2][8][4])
{
#pragma unroll
    for (int mt = 0; mt < 2; ++mt)
#pragma unroll
        for (int nt = 0; nt < 8; ++nt)
#pragma unroll
            for (int e = 0; e < 4; ++e) acc[mt][nt][e] = 0.0f;

#pragma unroll
    for (int ks = 0; ks < 8; ++ks) {
        int kc = ks * 8;
        unsigned a[2][4];
#pragma unroll
        for (int mt = 0; mt < 2; ++mt) {
            int r = wm * 32 + mt * 16 + g;
            a[mt][0] = Qs[(r) * QK_LDS + kc + tg];
            a[mt][1] = Qs[(r + 8) * QK_LDS + kc + tg];
            a[mt][2] = Qs[(r) * QK_LDS + kc + tg + 4];
            a[mt][3] = Qs[(r + 8) * QK_LDS + kc + tg + 4];
        }
        unsigned b[8][2];
#pragma unroll
        for (int nt = 0; nt < 8; ++nt) {
            int n = wn * 64 + nt * 8 + g;
            b[nt][0] = Ks[n * QK_LDS + kc + tg];
            b[nt][1] = Ks[n * QK_LDS + kc + tg + 4];
        }
#pragma unroll
        for (int mt = 0; mt < 2; ++mt)
#pragma unroll
            for (int nt = 0; nt < 8; ++nt) {
                asm volatile(
                    "mma.sync.aligned.m16n8k8.row.col.f32.tf32.tf32.f32 "
                    "{%0,%1,%2,%3}, {%4,%5,%6,%7}, {%8,%9}, {%0,%1,%2,%3};"
                    : "+f"(acc[mt][nt][0]), "+f"(acc[mt][nt][1]),
                      "+f"(acc[mt][nt][2]), "+f"(acc[mt][nt][3])
                    : "r"(a[mt][0]), "r"(a[mt][1]), "r"(a[mt][2]), "r"(a[mt][3]),
                      "r"(b[nt][0]), "r"(b[nt][1]));
            }
    }
}

__device__ __forceinline__ void stage_qk(
    const float* __restrict__ G, unsigned* S, int tid)
{
#pragma unroll
    for (int p = 0; p < 8; ++p) {
        int r = (tid >> 4) + p * 16;
        int c = (tid & 15) * 4;
        float4 v = *(const float4*)(G + r * DHh + c);
        unsigned* s = S + r * QK_LDS + c;
        s[0] = f2tf32(v.x); s[1] = f2tf32(v.y);
        s[2] = f2tf32(v.z); s[3] = f2tf32(v.w);
    }
}

__global__ __launch_bounds__(256) void qk_rowmax(
    const float* __restrict__ Q, const float* __restrict__ K,
    unsigned* __restrict__ rmaxU)
{
    extern __shared__ unsigned sm[];
    unsigned* Qs = sm;
    unsigned* Ks = sm + 128 * QK_LDS;
    unsigned* rmaxs = sm + 2 * 128 * QK_LDS;

    int tid = threadIdx.x;
    int wid = tid >> 5, lane = tid & 31;
    int wm = wid & 3, wn = wid >> 2;
    int g = lane >> 2, tg = lane & 3;

    int khalf = blockIdx.x;
    int q0 = blockIdx.y * 128;
    int bh = blockIdx.z;

    for (int r = tid; r < 128; r += 256) rmaxs[r] = 0u;
    stage_qk(Q + ((long)bh * Ss + q0) * DHh, Qs, tid);
    __syncthreads();

    float acc[2][8][4];
    for (int t = khalf * 8; t < khalf * 8 + 8; ++t) {
        stage_qk(K + ((long)bh * Ss + t * 128) * DHh, Ks, tid);
        __syncthreads();

        tile_mma(Qs, Ks, wm, wn, g, tg, acc);

#pragma unroll
        for (int mt = 0; mt < 2; ++mt) {
            float m0 = -3e38f, m1 = -3e38f;
#pragma unroll
            for (int nt = 0; nt < 8; ++nt) {
                m0 = fmaxf(m0, fmaxf(acc[mt][nt][0], acc[mt][nt][1]));
                m1 = fmaxf(m1, fmaxf(acc[mt][nt][2], acc[mt][nt][3]));
            }
#pragma unroll
            for (int off = 1; off <= 2; off <<= 1) {
                m0 = fmaxf(m0, __shfl_xor_sync(0xffffffffu, m0, off));
                m1 = fmaxf(m1, __shfl_xor_sync(0xffffffffu, m1, off));
            }
            if (tg == 0) {
                atomicMax(&rmaxs[wm * 32 + mt * 16 + g], enc_f(m0));
                atomicMax(&rmaxs[wm * 32 + mt * 16 + g + 8], enc_f(m1));
            }
        }
        __syncthreads();
    }

    long rowg0 = (long)bh * Ss + q0;
    for (int r = tid; r < 128; r += 256)
        atomicMax(&rmaxU[rowg0 + r], rmaxs[r]);
}

__global__ __launch_bounds__(256) void qk_screen2(
    const float* __restrict__ Q, const float* __restrict__ K,
    const unsigned* __restrict__ rmaxU,
    unsigned short* __restrict__ cand, int* __restrict__ ccnt)
{
    extern __shared__ unsigned sm[];
    unsigned* Qs = sm;
    unsigned* Ks = sm + 128 * QK_LDS;
    float* thrs = (float*)(sm + 2 * 128 * QK_LDS);
    int* cnts = (int*)(thrs + 128);

    int tid = threadIdx.x;
    int wid = tid >> 5, lane = tid & 31;
    int wm = wid & 3, wn = wid >> 2;
    int g = lane >> 2, tg = lane & 3;
    int qb = lane & ~3;

    int khalf = blockIdx.x;
    int q0 = blockIdx.y * 128;
    int bh = blockIdx.z;
    long rowg0 = (long)bh * Ss + q0;

    for (int r = tid; r < 128; r += 256) {
        cnts[r] = 0;
        thrs[r] = dec_f(rmaxU[rowg0 + r]) - 1.02f;
    }
    stage_qk(Q + ((long)bh * Ss + q0) * DHh, Qs, tid);
    __syncthreads();

    float acc[2][8][4];
    for (int t = khalf * 8; t < khalf * 8 + 8; ++t) {
        stage_qk(K + ((long)bh * Ss + t * 128) * DHh, Ks, tid);
        __syncthreads();

        tile_mma(Qs, Ks, wm, wn, g, tg, acc);

        for (int phase = 0; phase < 2; ++phase) {
            if (wn == phase) {
#pragma unroll
                for (int mt = 0; mt < 2; ++mt) {
#pragma unroll
                    for (int hf = 0; hf < 2; ++hf) {
                        int r = wm * 32 + mt * 16 + g + hf * 8;
                        float thr = thrs[r];
                        unsigned m = 0;
#pragma unroll
                        for (int nt = 0; nt < 8; ++nt) {
#pragma unroll
                            for (int ee = 0; ee < 2; ++ee)
                                if (acc[mt][nt][hf * 2 + ee] > thr)
                                    m |= 1u << (nt * 2 + ee);
                        }
                        int c = __popc(m);
                        int c0 = __shfl_sync(0xffffffffu, c, qb);
                        int c1 = __shfl_sync(0xffffffffu, c, qb + 1);
                        int c2 = __shfl_sync(0xffffffffu, c, qb + 2);
                        int c3 = __shfl_sync(0xffffffffu, c, qb + 3);
                        int pre = (tg > 0 ? c0 : 0) + (tg > 1 ? c1 : 0) + (tg > 2 ? c2 : 0);
                        int tot = c0 + c1 + c2 + c3;
                        int base = cnts[r];
                        int pos = base + pre;
                        unsigned short* dst =
                            cand + (rowg0 + r) * CAPS + khalf * HCAP;
                        while (m) {
                            int bit = __ffs(m) - 1; m &= m - 1;
                            int j = t * 128 + wn * 64 + (bit >> 1) * 8 + tg * 2 + (bit & 1);
                            if (pos < HCAP) dst[pos] = (unsigned short)j;
                            ++pos;
                        }
                        __syncwarp();
                        if (tg == 0) cnts[r] = base + tot;
                        __syncwarp();
                    }
                }
            }
            __syncthreads();
        }
    }

    for (int r = tid; r < 128; r += 256)
        ccnt[(rowg0 + r) * 2 + khalf] = cnts[r];
}

// ---------------------------------------------------------------------------
// Finish v2: lane-parallel exact recompute (no shuffle chains), Michelot,
// heads, avg. Overflow: block-parallel zrow + split heads (all deterministic).
// ---------------------------------------------------------------------------
__global__ __launch_bounds__(256) void sparse_final(
    const unsigned short* __restrict__ cand, const int* __restrict__ ccnt,
    const unsigned* __restrict__ rmaxU,
    const float* __restrict__ Q, const float* __restrict__ K,
    const float* __restrict__ V,
    float* __restrict__ heads, float* __restrict__ avg_out)
{
    __shared__ float s_z[Hh][CAPS];
    __shared__ short s_j[Hh][CAPS];
    __shared__ __align__(16) float s_q[Hh][DHh];
    __shared__ float s_tau[Hh];
    __shared__ int   s_cnt[Hh];
    __shared__ int   s_over[Hh];
    __shared__ float s_zrow[Ss];
    __shared__ float s_hpart[4][DHh];
    __shared__ float s_part[8];
    __shared__ int   s_partc[8];
    __shared__ float s_bcast;

    int row = blockIdx.x;
    int b = row >> 11;
    int i = row & 2047;
    int tid = threadIdx.x;
    int w = tid >> 5;
    int lane = tid & 31;

    long bhrow = ((long)b * Hh + w) * Ss + i;
    const float* Qrow = Q + bhrow * DHh;
    const float* Kbh  = K + (((long)b * Hh + w) * Ss) * (long)DHh;
    const float* Vb   = V + (long)b * Ss * DHh;
    float q0 = Qrow[lane], q1 = Qrow[lane + 32];
    s_q[w][lane] = q0;
    s_q[w][lane + 32] = q1;
    float rmax = dec_f(rmaxU[bhrow]);

    int n0 = ccnt[bhrow * 2];
    int n1 = ccnt[bhrow * 2 + 1];
    float rv[8];
#pragma unroll
    for (int k = 0; k < 8; ++k) rv[k] = 0.0f;

    if (n0 <= HCAP && n1 <= HCAP) {
        int n = n0 + n1;
        if (lane == 0) s_over[w] = 0;
        const unsigned short* cr = cand + bhrow * CAPS;
        for (int e = lane; e < n0; e += 32) s_j[w][e] = (short)cr[e];
        for (int e = lane; e < n1; e += 32) s_j[w][n0 + e] = (short)cr[HCAP + e];
        __syncwarp();

        // lane-parallel exact fp32 recompute: one candidate per lane
        for (int e = lane; e < n; e += 32) {
            const float4* Kr = (const float4*)(Kbh + (long)s_j[w][e] * DHh);
            float dot = 0.0f;
#pragma unroll
            for (int d4 = 0; d4 < 16; ++d4) {
                float4 kv = Kr[d4];
                float4 qv = *(const float4*)(&s_q[w][d4 * 4]);
                dot += qv.x * kv.x + qv.y * kv.y + qv.z * kv.z + qv.w * kv.w;
            }
            s_z[w][e] = dot;
        }
        __syncwarp();

        // exact tau: Michelot over candidate superset
        float tau = rmax - 1.02f;
        for (int it = 0; it < 48; ++it) {
            float s = 0.0f; int c = 0;
            for (int e2 = lane; e2 < n; e2 += 32) {
                float zz = s_z[w][e2];
                if (zz > tau) { s += zz; c++; }
            }
#pragma unroll
            for (int off = 16; off; off >>= 1) {
                s += __shfl_xor_sync(0xffffffffu, s, off);
                c += __shfl_xor_sync(0xffffffffu, c, off);
            }
            float nt2 = (s - 1.0f) / (float)c;
            if (nt2 == tau) break;
            tau = nt2;
        }
        if (lane == 0) { s_tau[w] = tau; s_cnt[w] = n; }

        // heads: serial over candidates (deterministic), lane = dim
        float o0 = 0.0f, o1 = 0.0f;
        for (int e2 = 0; e2 < n; ++e2) {
            float p = s_z[w][e2] - tau;
            if (p > 0.0f) {
                const float* Vr = Vb + (long)s_j[w][e2] * DHh;
                o0 += p * Vr[lane];
                o1 += p * Vr[lane + 32];
            }
        }
        long hbase = (long)row * Dd + w * DHh;
        heads[hbase + lane] = o0;
        heads[hbase + lane + 32] = o1;
    } else {
        if (lane == 0) { s_over[w] = 1; s_cnt[w] = 0; s_tau[w] = 0.0f; }
    }

    __syncthreads();

    // deferred overflow heads: block-parallel exact solve on shared z-row
    for (int h = 0; h < Hh; ++h) {
        if (!s_over[h]) continue;

        long bhrowH = ((long)b * Hh + h) * Ss + i;
        const float* KbhH = K + (((long)b * Hh + h) * Ss) * (long)DHh;

        // 1) zrow: 256 threads x 8 private dots (q broadcast from shared)
#pragma unroll
        for (int k = 0; k < 8; ++k) {
            int j = tid + k * 256;
            const float4* Kr = (const float4*)(KbhH + (long)j * DHh);
            float dot = 0.0f;
#pragma unroll
            for (int d4 = 0; d4 < 16; ++d4) {
                float4 kv = Kr[d4];
                float4 qv = *(const float4*)(&s_q[h][d4 * 4]);
                dot += qv.x * kv.x + qv.y * kv.y + qv.z * kv.z + qv.w * kv.w;
            }
            s_zrow[j] = dot;
        }
        __syncthreads();

        // 2) Michelot on shared row (deterministic tree reduction)
        float tau = dec_f(rmaxU[bhrowH]) - 1.02f;
        for (int it = 0; it < 48; ++it) {
            float s = 0.0f; int c = 0;
#pragma unroll
            for (int k = 0; k < 8; ++k) {
                float zz = s_zrow[tid + k * 256];
                if (zz > tau) { s += zz; c++; }
            }
#pragma unroll
            for (int off = 16; off; off >>= 1) {
                s += __shfl_xor_sync(0xffffffffu, s, off);
                c += __shfl_xor_sync(0xffffffffu, c, off);
            }
            if (lane == 0) { s_part[w] = s; s_partc[w] = c; }
            __syncthreads();
            if (tid == 0) {
                float S = 0.0f; int C = 0;
#pragma unroll
                for (int k = 0; k < 8; ++k) { S += s_part[k]; C += s_partc[k]; }
                s_bcast = (S - 1.0f) / (float)C;
            }
            __syncthreads();
            float nt2 = s_bcast;
            bool done = (nt2 == tau);
            tau = nt2;
            __syncthreads();
            if (done) break;
        }
        if (tid == 0) s_tau[h] = tau;

        // 3) heads: 4 key-chunks x 64 dims, fixed-order combine
        {
            int d = tid & 63;
            int ck = tid >> 6;
            float o = 0.0f;
            for (int j = ck * 512; j < ck * 512 + 512; ++j) {
                float p = s_zrow[j] - tau;
                if (p > 0.0f) o += p * Vb[(long)j * DHh + d];
            }
            s_hpart[ck][d] = o;
        }
        __syncthreads();
        if (tid < DHh) {
            float o = ((s_hpart[0][tid] + s_hpart[1][tid]) + s_hpart[2][tid])
                      + s_hpart[3][tid];
            heads[(long)row * Dd + h * DHh + tid] = o;
        }

        // 4) avg contribution (ownership: thread owns j%256==tid)
#pragma unroll
        for (int k = 0; k < 8; ++k) {
            float p = s_zrow[tid + k * 256] - tau;
            if (p > 0.0f) rv[k] += p;
        }
        __syncthreads();
    }

    // avg_attention: ownership scan over normal heads' candidate lists
#pragma unroll
    for (int h = 0; h < Hh; ++h) {
        int c = s_cnt[h];
        float th = s_tau[h];
        for (int e = 0; e < c; ++e) {
            int j = s_j[h][e];
            if ((j & 255) == tid) {
                float p = s_z[h][e] - th;
                if (p > 0.0f) rv[j >> 8] += p;
            }
        }
    }
    long abase = ((long)b * Ss + i) * (long)Ss;
#pragma unroll
    for (int k = 0; k < 8; ++k)
        avg_out[abase + tid + k * 256] = 0.125f * rv[k];
}

// ---------------------------------------------------------------------------
extern "C" void kernel_launch(void* const* d_in, const int* in_sizes, int n_in,
                              void* d_out, int out_size)
{
    const float* x    = (const float*)d_in[0];
    const float* Wq   = (const float*)d_in[1];
    const float* bq   = (const float*)d_in[2];
    const float* Wk   = (const float*)d_in[3];
    const float* bk   = (const float*)d_in[4];
    const float* Wv   = (const float*)d_in[5];
    const float* bv   = (const float*)d_in[6];
    const float* Wout = (const float*)d_in[7];
    const float* bout = (const float*)d_in[8];

    float* out   = (float*)d_out;
    float* x_out = out;                              // [B,S,D]
    float* avg   = out + (long)Bb * Ss * Dd;         // [B,S,S]

    float *Qp, *Kp, *Vp, *Hp;
    unsigned* Rp;
    unsigned short* Cp;
    int* Np;
    cudaGetSymbolAddress((void**)&Qp, g_Q);
    cudaGetSymbolAddress((void**)&Kp, g_K);
    cudaGetSymbolAddress((void**)&Vp, g_V);
    cudaGetSymbolAddress((void**)&Hp, g_heads);
    cudaGetSymbolAddress((void**)&Cp, g_cand);
    cudaGetSymbolAddress((void**)&Np, g_ccnt);
    cudaGetSymbolAddress((void**)&Rp, g_rmaxU);

    cudaFuncSetAttribute(qk_rowmax,
                         cudaFuncAttributeMaxDynamicSharedMemorySize, RMX_SMEM);
    cudaFuncSetAttribute(qk_screen2,
                         cudaFuncAttributeMaxDynamicSharedMemorySize, SCR_SMEM);
    cudaFuncSetAttribute(proj3t,
                         cudaFuncAttributeMaxDynamicSharedMemorySize, G3_SMEM);
    cudaFuncSetAttribute(wout3t,
                         cudaFuncAttributeMaxDynamicSharedMemorySize, G3_SMEM);

    // rowmax init: encoded 0 < enc(any finite float)
    cudaMemsetAsync(Rp, 0, Bb * Hh * Ss * sizeof(unsigned));

    // fused Q/K/V projections (3xtf32 tensor cores)
    proj3t<<<dim3(32, 17, 1), 256, G3_SMEM>>>(
        x, Wq, bq, Wk, bk, Wv, bv, Qp, Kp, Vp);

    // exact-threshold screening, K-half parallel
    qk_rowmax<<<dim3(2, 16, Bb * Hh), 256, RMX_SMEM>>>(Qp, Kp, Rp);
    qk_screen2<<<dim3(2, 16, Bb * Hh), 256, SCR_SMEM>>>(Qp, Kp, Rp, Cp, Np);

    // exact sparsemax + heads + avg from candidate lists
    sparse_final<<<Bb * Ss, 256>>>(Cp, Np, Rp, Qp, Kp, Vp, Hp, avg);

    // x_out = heads @ Wout + bout (3xtf32 tensor cores)
    wout3t<<<dim3(32, 8, 1), 256, G3_SMEM>>>(Hp, Wout, bout, x_out);
}

// round 16
// speedup vs baseline: 1.2614x; 1.2614x over previous
#include <cuda_runtime.h>

#define Bb 2
#define Ss 2048
#define Dd 512
#define Hh 8
#define DHh 64
#define CAPS 256     // total candidate cap per row (two 128-entry halves)
#define HCAP 128     // per-half cap

// Scratch (device globals: no runtime allocation allowed)
__device__ float          g_Q[Bb * Hh * Ss * DHh];       // [B,H,S,dh]  8 MB
__device__ float          g_K[Bb * Hh * Ss * DHh];       // [B,H,S,dh]  8 MB
__device__ float          g_V[Bb * Ss * DHh];            // [B,S,dh]    1 MB
__device__ float          g_heads[Bb * Ss * Dd];         // [B,S,D]     8 MB
__device__ unsigned short g_cand[Bb * Hh * Ss * CAPS];   // cand indices (2 halves)
__device__ int            g_ccnt[Bb * Hh * Ss * 2];      // per-half counts
__device__ unsigned       g_rmaxU[Bb * Hh * Ss];         // encoded row maxes

__device__ __forceinline__ unsigned enc_f(float f) {
    unsigned b = __float_as_uint(f);
    return (f >= 0.0f) ? (b | 0x80000000u) : ~b;
}
__device__ __forceinline__ float dec_f(unsigned u) {
    return (u & 0x80000000u) ? __uint_as_float(u & 0x7fffffffu)
                             : __uint_as_float(~u);
}
__device__ __forceinline__ unsigned f2tf32(float f) {
    unsigned u;
    asm("cvt.rna.tf32.f32 %0, %1;" : "=r"(u) : "f"(f));
    return u;
}

#define MMA3(d, a, b) asm volatile( \
    "mma.sync.aligned.m16n8k8.row.col.f32.tf32.tf32.f32 " \
    "{%0,%1,%2,%3}, {%4,%5,%6,%7}, {%8,%9}, {%0,%1,%2,%3};" \
    : "+f"(d[0]), "+f"(d[1]), "+f"(d[2]), "+f"(d[3]) \
    : "r"(a[0]), "r"(a[1]), "r"(a[2]), "r"(a[3]), "r"(b[0]), "r"(b[1]))

// ---------------------------------------------------------------------------
// 3xTF32 GEMM core (validated R11): C[128x64] = A(MxK)@W(KxN)+bias, K=512
// ---------------------------------------------------------------------------
#define G3_SMEM ((2 * 128 * 36 + 2 * 64 * 36) * 4)   // 55296 B

__device__ __forceinline__ void gemm3t_tile(
    const float* __restrict__ A, int lda,
    const float* __restrict__ W, int ldw,
    const float* __restrict__ bias,
    float* __restrict__ C,
    int m0, int n0, int ldc, int headMajor,
    unsigned* Ah, unsigned* Al, unsigned* Bh, unsigned* Bl)
{
    int tid = threadIdx.x;
    int wid = tid >> 5, lane = tid & 31;
    int wm = wid & 3, wn = wid >> 2;
    int g = lane >> 2, tg = lane & 3;

    float acc[2][4][4];
#pragma unroll
    for (int mt = 0; mt < 2; ++mt)
#pragma unroll
        for (int nt = 0; nt < 4; ++nt)
#pragma unroll
            for (int e = 0; e < 4; ++e) acc[mt][nt][e] = 0.0f;

    int arow = tid >> 1;
    int acb = (tid & 1) * 16;
    int bn = tid & 63;
    int bkb = (tid >> 6) * 8;

    for (int k0 = 0; k0 < Dd; k0 += 32) {
#pragma unroll
        for (int p = 0; p < 4; ++p) {
            int c = acb + p * 4;
            float4 v = *(const float4*)(A + (long)(m0 + arow) * lda + k0 + c);
            float vv[4] = {v.x, v.y, v.z, v.w};
#pragma unroll
            for (int u = 0; u < 4; ++u) {
                unsigned hi = f2tf32(vv[u]);
                Ah[arow * 36 + c + u] = hi;
                Al[arow * 36 + c + u] = f2tf32(vv[u] - __uint_as_float(hi));
            }
        }
#pragma unroll
        for (int u = 0; u < 8; ++u) {
            float v = W[(long)(k0 + bkb + u) * ldw + n0 + bn];
            unsigned hi = f2tf32(v);
            Bh[bn * 36 + bkb + u] = hi;
            Bl[bn * 36 + bkb + u] = f2tf32(v - __uint_as_float(hi));
        }
        __syncthreads();

#pragma unroll
        for (int kc = 0; kc < 32; kc += 8) {
            unsigned ah[2][4], al[2][4], bh[4][2], bl[4][2];
#pragma unroll
            for (int mt = 0; mt < 2; ++mt) {
                int r = wm * 32 + mt * 16 + g;
                ah[mt][0] = Ah[r * 36 + kc + tg];
                ah[mt][1] = Ah[(r + 8) * 36 + kc + tg];
                ah[mt][2] = Ah[r * 36 + kc + tg + 4];
                ah[mt][3] = Ah[(r + 8) * 36 + kc + tg + 4];
                al[mt][0] = Al[r * 36 + kc + tg];
                al[mt][1] = Al[(r + 8) * 36 + kc + tg];
                al[mt][2] = Al[r * 36 + kc + tg + 4];
                al[mt][3] = Al[(r + 8) * 36 + kc + tg + 4];
            }
#pragma unroll
            for (int nt = 0; nt < 4; ++nt) {
                int n = wn * 32 + nt * 8 + g;
                bh[nt][0] = Bh[n * 36 + kc + tg];
                bh[nt][1] = Bh[n * 36 + kc + tg + 4];
                bl[nt][0] = Bl[n * 36 + kc + tg];
                bl[nt][1] = Bl[n * 36 + kc + tg + 4];
            }
#pragma unroll
            for (int mt = 0; mt < 2; ++mt)
#pragma unroll
                for (int nt = 0; nt < 4; ++nt) {
                    MMA3(acc[mt][nt], ah[mt], bl[nt]);
                    MMA3(acc[mt][nt], al[mt], bh[nt]);
                    MMA3(acc[mt][nt], ah[mt], bh[nt]);
                }
        }
        __syncthreads();
    }

    int cb = wn * 32 + tg * 2;
#pragma unroll
    for (int mt = 0; mt < 2; ++mt) {
#pragma unroll
        for (int nt = 0; nt < 4; ++nt) {
            int r0 = m0 + wm * 32 + mt * 16 + g;
            int c = cb + nt * 8;
            float2 b2 = *(const float2*)(bias + n0 + c);
            float o0 = acc[mt][nt][0] + b2.x;
            float o1 = acc[mt][nt][1] + b2.y;
            float o2 = acc[mt][nt][2] + b2.x;
            float o3 = acc[mt][nt][3] + b2.y;
            if (headMajor) {
                int hh = n0 >> 6;
                int bb0 = r0 >> 11, ss0 = r0 & 2047;
                *(float2*)(C + ((((long)bb0 * Hh + hh) * Ss) + ss0) * DHh + c) =
                    make_float2(o0, o1);
                int r1 = r0 + 8;
                int bb1 = r1 >> 11, ss1 = r1 & 2047;
                *(float2*)(C + ((((long)bb1 * Hh + hh) * Ss) + ss1) * DHh + c) =
                    make_float2(o2, o3);
            } else {
                *(float2*)(C + (long)r0 * ldc + n0 + c) = make_float2(o0, o1);
                *(float2*)(C + (long)(r0 + 8) * ldc + n0 + c) = make_float2(o2, o3);
            }
        }
    }
}

__global__ __launch_bounds__(256) void proj3t(
    const float* __restrict__ x,
    const float* __restrict__ Wq, const float* __restrict__ bq,
    const float* __restrict__ Wk, const float* __restrict__ bk,
    const float* __restrict__ Wv, const float* __restrict__ bv,
    float* __restrict__ Qo, float* __restrict__ Ko, float* __restrict__ Vo)
{
    extern __shared__ unsigned sm3[];
    unsigned* Ah = sm3;
    unsigned* Al = sm3 + 128 * 36;
    unsigned* Bh = sm3 + 2 * 128 * 36;
    unsigned* Bl = Bh + 64 * 36;

    int y = blockIdx.y;
    int m0 = blockIdx.x * 128;
    if (y < 8)
        gemm3t_tile(x, Dd, Wq, Dd, bq, Qo, m0, y * 64, 0, 1, Ah, Al, Bh, Bl);
    else if (y < 16)
        gemm3t_tile(x, Dd, Wk, Dd, bk, Ko, m0, (y - 8) * 64, 0, 1, Ah, Al, Bh, Bl);
    else
        gemm3t_tile(x, Dd, Wv, DHh, bv, Vo, m0, 0, DHh, 0, Ah, Al, Bh, Bl);
}

__global__ __launch_bounds__(256) void wout3t(
    const float* __restrict__ A, const float* __restrict__ W,
    const float* __restrict__ bias, float* __restrict__ C)
{
    extern __shared__ unsigned sm3[];
    unsigned* Ah = sm3;
    unsigned* Al = sm3 + 128 * 36;
    unsigned* Bh = sm3 + 2 * 128 * 36;
    unsigned* Bl = Bh + 64 * 36;
    gemm3t_tile(A, Dd, W, Dd, bias, C,
                blockIdx.x * 128, blockIdx.y * 64, Dd, 0, Ah, Al, Bh, Bl);
}

// ---------------------------------------------------------------------------
// QK screening, K-half parallel (grid 2 x 16 x 16 = 512 CTAs per kernel).
// ---------------------------------------------------------------------------
#define QK_LDS 68
#define RMX_SMEM (2 * 128 * QK_LDS * 4 + 128 * 4)
#define SCR_SMEM (2 * 128 * QK_LDS * 4 + 128 * 4 + 128 * 4)

__device__ __forceinline__ void tile_mma(
    const unsigned* Qs, const unsigned* Ks,
    int wm, int wn, int g, int tg, float acc[2][8][4])
{
#pragma unroll
    for (int mt = 0; mt < 2; ++mt)
#pragma unroll
        for (int nt = 0; nt < 8; ++nt)
#pragma unroll
            for (int e = 0; e < 4; ++e) acc[mt][nt][e] = 0.0f;

#pragma unroll
    for (int ks = 0; ks < 8; ++ks) {
        int kc = ks * 8;
        unsigned a[2][4];
#pragma unroll
        for (int mt = 0; mt < 2; ++mt) {
            int r = wm * 32 + mt * 16 + g;
            a[mt][0] = Qs[(r) * QK_LDS + kc + tg];
            a[mt][1] = Qs[(r + 8) * QK_LDS + kc + tg];
            a[mt][2] = Qs[(r) * QK_LDS + kc + tg + 4];
            a[mt][3] = Qs[(r + 8) * QK_LDS + kc + tg + 4];
        }
        unsigned b[8][2];
#pragma unroll
        for (int nt = 0; nt < 8; ++nt) {
            int n = wn * 64 + nt * 8 + g;
            b[nt][0] = Ks[n * QK_LDS + kc + tg];
            b[nt][1] = Ks[n * QK_LDS + kc + tg + 4];
        }
#pragma unroll
        for (int mt = 0; mt < 2; ++mt)
#pragma unroll
            for (int nt = 0; nt < 8; ++nt) {
                asm volatile(
                    "mma.sync.aligned.m16n8k8.row.col.f32.tf32.tf32.f32 "
                    "{%0,%1,%2,%3}, {%4,%5,%6,%7}, {%8,%9}, {%0,%1,%2,%3};"
                    : "+f"(acc[mt][nt][0]), "+f"(acc[mt][nt][1]),
                      "+f"(acc[mt][nt][2]), "+f"(acc[mt][nt][3])
                    : "r"(a[mt][0]), "r"(a[mt][1]), "r"(a[mt][2]), "r"(a[mt][3]),
                      "r"(b[nt][0]), "r"(b[nt][1]));
            }
    }
}

__device__ __forceinline__ void stage_qk(
    const float* __restrict__ G, unsigned* S, int tid)
{
#pragma unroll
    for (int p = 0; p < 8; ++p) {
        int r = (tid >> 4) + p * 16;
        int c = (tid & 15) * 4;
        float4 v = *(const float4*)(G + r * DHh + c);
        unsigned* s = S + r * QK_LDS + c;
        s[0] = f2tf32(v.x); s[1] = f2tf32(v.y);
        s[2] = f2tf32(v.z); s[3] = f2tf32(v.w);
    }
}

__global__ __launch_bounds__(256) void qk_rowmax(
    const float* __restrict__ Q, const float* __restrict__ K,
    unsigned* __restrict__ rmaxU)
{
    extern __shared__ unsigned sm[];
    unsigned* Qs = sm;
    unsigned* Ks = sm + 128 * QK_LDS;
    unsigned* rmaxs = sm + 2 * 128 * QK_LDS;

    int tid = threadIdx.x;
    int wid = tid >> 5, lane = tid & 31;
    int wm = wid & 3, wn = wid >> 2;
    int g = lane >> 2, tg = lane & 3;

    int khalf = blockIdx.x;
    int q0 = blockIdx.y * 128;
    int bh = blockIdx.z;

    for (int r = tid; r < 128; r += 256) rmaxs[r] = 0u;
    stage_qk(Q + ((long)bh * Ss + q0) * DHh, Qs, tid);
    __syncthreads();

    float acc[2][8][4];
    for (int t = khalf * 8; t < khalf * 8 + 8; ++t) {
        stage_qk(K + ((long)bh * Ss + t * 128) * DHh, Ks, tid);
        __syncthreads();

        tile_mma(Qs, Ks, wm, wn, g, tg, acc);

#pragma unroll
        for (int mt = 0; mt < 2; ++mt) {
            float m0 = -3e38f, m1 = -3e38f;
#pragma unroll
            for (int nt = 0; nt < 8; ++nt) {
                m0 = fmaxf(m0, fmaxf(acc[mt][nt][0], acc[mt][nt][1]));
                m1 = fmaxf(m1, fmaxf(acc[mt][nt][2], acc[mt][nt][3]));
            }
#pragma unroll
            for (int off = 1; off <= 2; off <<= 1) {
                m0 = fmaxf(m0, __shfl_xor_sync(0xffffffffu, m0, off));
                m1 = fmaxf(m1, __shfl_xor_sync(0xffffffffu, m1, off));
            }
            if (tg == 0) {
                atomicMax(&rmaxs[wm * 32 + mt * 16 + g], enc_f(m0));
                atomicMax(&rmaxs[wm * 32 + mt * 16 + g + 8], enc_f(m1));
            }
        }
        __syncthreads();
    }

    long rowg0 = (long)bh * Ss + q0;
    for (int r = tid; r < 128; r += 256)
        atomicMax(&rmaxU[rowg0 + r], rmaxs[r]);
}

__global__ __launch_bounds__(256) void qk_screen2(
    const float* __restrict__ Q, const float* __restrict__ K,
    const unsigned* __restrict__ rmaxU,
    unsigned short* __restrict__ cand, int* __restrict__ ccnt)
{
    extern __shared__ unsigned sm[];
    unsigned* Qs = sm;
    unsigned* Ks = sm + 128 * QK_LDS;
    float* thrs = (float*)(sm + 2 * 128 * QK_LDS);
    int* cnts = (int*)(thrs + 128);

    int tid = threadIdx.x;
    int wid = tid >> 5, lane = tid & 31;
    int wm = wid & 3, wn = wid >> 2;
    int g = lane >> 2, tg = lane & 3;
    int qb = lane & ~3;

    int khalf = blockIdx.x;
    int q0 = blockIdx.y * 128;
    int bh = blockIdx.z;
    long rowg0 = (long)bh * Ss + q0;

    for (int r = tid; r < 128; r += 256) {
        cnts[r] = 0;
        thrs[r] = dec_f(rmaxU[rowg0 + r]) - 1.02f;
    }
    stage_qk(Q + ((long)bh * Ss + q0) * DHh, Qs, tid);
    __syncthreads();

    float acc[2][8][4];
    for (int t = khalf * 8; t < khalf * 8 + 8; ++t) {
        stage_qk(K + ((long)bh * Ss + t * 128) * DHh, Ks, tid);
        __syncthreads();

        tile_mma(Qs, Ks, wm, wn, g, tg, acc);

        for (int phase = 0; phase < 2; ++phase) {
            if (wn == phase) {
#pragma unroll
                for (int mt = 0; mt < 2; ++mt) {
#pragma unroll
                    for (int hf = 0; hf < 2; ++hf) {
                        int r = wm * 32 + mt * 16 + g + hf * 8;
                        float thr = thrs[r];
                        unsigned m = 0;
#pragma unroll
                        for (int nt = 0; nt < 8; ++nt) {
#pragma unroll
                            for (int ee = 0; ee < 2; ++ee)
                                if (acc[mt][nt][hf * 2 + ee] > thr)
                                    m |= 1u << (nt * 2 + ee);
                        }
                        int c = __popc(m);
                        int c0 = __shfl_sync(0xffffffffu, c, qb);
                        int c1 = __shfl_sync(0xffffffffu, c, qb + 1);
                        int c2 = __shfl_sync(0xffffffffu, c, qb + 2);
                        int c3 = __shfl_sync(0xffffffffu, c, qb + 3);
                        int pre = (tg > 0 ? c0 : 0) + (tg > 1 ? c1 : 0) + (tg > 2 ? c2 : 0);
                        int tot = c0 + c1 + c2 + c3;
                        int base = cnts[r];
                        int pos = base + pre;
                        unsigned short* dst =
                            cand + (rowg0 + r) * CAPS + khalf * HCAP;
                        while (m) {
                            int bit = __ffs(m) - 1; m &= m - 1;
                            int j = t * 128 + wn * 64 + (bit >> 1) * 8 + tg * 2 + (bit & 1);
                            if (pos < HCAP) dst[pos] = (unsigned short)j;
                            ++pos;
                        }
                        __syncwarp();
                        if (tg == 0) cnts[r] = base + tot;
                        __syncwarp();
                    }
                }
            }
            __syncthreads();
        }
    }

    for (int r = tid; r < 128; r += 256)
        ccnt[(rowg0 + r) * 2 + khalf] = cnts[r];
}

// ---------------------------------------------------------------------------
// Finish v3: occupancy-friendly (<=64 regs target), lane-parallel recompute,
// phased parallel avg accumulation (unique writer per address per phase),
// warp-redundant barrier-free overflow Michelot. All deterministic.
// ---------------------------------------------------------------------------
__global__ __launch_bounds__(256, 4) void sparse_final(
    const unsigned short* __restrict__ cand, const int* __restrict__ ccnt,
    const unsigned* __restrict__ rmaxU,
    const float* __restrict__ Q, const float* __restrict__ K,
    const float* __restrict__ V,
    float* __restrict__ heads, float* __restrict__ avg_out)
{
    __shared__ float s_z[Hh][CAPS];
    __shared__ short s_j[Hh][CAPS];
    __shared__ __align__(16) float s_q[Hh][DHh];
    __shared__ float s_tau[Hh];
    __shared__ int   s_cnt[Hh];
    __shared__ int   s_over[Hh];
    __shared__ float s_avg[Ss];
    __shared__ float s_zrow[Ss];
    __shared__ float s_hp0[Hh][DHh / 2];
    __shared__ float s_hp1[Hh][DHh / 2];

    int row = blockIdx.x;
    int b = row >> 11;
    int i = row & 2047;
    int tid = threadIdx.x;
    int w = tid >> 5;
    int lane = tid & 31;

    // zero shared avg row (no other writer touches it before the barrier)
#pragma unroll
    for (int k = 0; k < 8; ++k) s_avg[tid + k * 256] = 0.0f;

    long bhrow = ((long)b * Hh + w) * Ss + i;
    const float* Qrow = Q + bhrow * DHh;
    const float* Kbh  = K + (((long)b * Hh + w) * Ss) * (long)DHh;
    const float* Vb   = V + (long)b * Ss * DHh;
    float q0 = Qrow[lane], q1 = Qrow[lane + 32];
    s_q[w][lane] = q0;
    s_q[w][lane + 32] = q1;
    float rmax = dec_f(rmaxU[bhrow]);

    int n0 = ccnt[bhrow * 2];
    int n1 = ccnt[bhrow * 2 + 1];

    if (n0 <= HCAP && n1 <= HCAP) {
        int n = n0 + n1;
        if (lane == 0) s_over[w] = 0;
        const unsigned short* cr = cand + bhrow * CAPS;
        for (int e = lane; e < n0; e += 32) s_j[w][e] = (short)cr[e];
        for (int e = lane; e < n1; e += 32) s_j[w][n0 + e] = (short)cr[HCAP + e];
        __syncwarp();

        // lane-parallel exact fp32 recompute (modest unroll: keep regs low)
        for (int e = lane; e < n; e += 32) {
            const float4* Kr = (const float4*)(Kbh + (long)s_j[w][e] * DHh);
            float dot = 0.0f;
#pragma unroll 4
            for (int d4 = 0; d4 < 16; ++d4) {
                float4 kv = Kr[d4];
                float4 qv = *(const float4*)(&s_q[w][d4 * 4]);
                dot += qv.x * kv.x + qv.y * kv.y + qv.z * kv.z + qv.w * kv.w;
            }
            s_z[w][e] = dot;
        }
        __syncwarp();

        // exact tau: Michelot over candidate superset
        float tau = rmax - 1.02f;
        for (int it = 0; it < 48; ++it) {
            float s = 0.0f; int c = 0;
            for (int e2 = lane; e2 < n; e2 += 32) {
                float zz = s_z[w][e2];
                if (zz > tau) { s += zz; c++; }
            }
#pragma unroll
            for (int off = 16; off; off >>= 1) {
                s += __shfl_xor_sync(0xffffffffu, s, off);
                c += __shfl_xor_sync(0xffffffffu, c, off);
            }
            float nt2 = (s - 1.0f) / (float)c;
            if (nt2 == tau) break;
            tau = nt2;
        }
        if (lane == 0) { s_tau[w] = tau; s_cnt[w] = n; }

        // heads: serial over candidates (p warp-uniform -> no divergence)
        float o0 = 0.0f, o1 = 0.0f;
        for (int e2 = 0; e2 < n; ++e2) {
            float p = s_z[w][e2] - tau;
            if (p > 0.0f) {
                const float* Vr = Vb + (long)s_j[w][e2] * DHh;
                o0 += p * Vr[lane];
                o1 += p * Vr[lane + 32];
            }
        }
        long hbase = (long)row * Dd + w * DHh;
        heads[hbase + lane] = o0;
        heads[hbase + lane + 32] = o1;
    } else {
        if (lane == 0) { s_over[w] = 1; s_cnt[w] = 0; s_tau[w] = 0.0f; }
    }

    __syncthreads();

    // avg accumulation, normal heads: 8 phases; within a phase all candidate
    // j are distinct -> parallel += race-free; barrier between phases.
#pragma unroll
    for (int h = 0; h < Hh; ++h) {
        int c = s_cnt[h];
        if (c > 0) {
            float th = s_tau[h];
            for (int e = tid; e < c; e += 256) {
                float p = s_z[h][e] - th;
                if (p > 0.0f) s_avg[s_j[h][e]] += p;
            }
        }
        __syncthreads();
    }

    // deferred overflow heads: block-parallel zrow, warp-redundant Michelot
    for (int h = 0; h < Hh; ++h) {
        if (!s_over[h]) continue;

        long bhrowH = ((long)b * Hh + h) * Ss + i;
        const float* KbhH = K + (((long)b * Hh + h) * Ss) * (long)DHh;

        // 1) zrow: 256 threads x 8 dots (q broadcast from shared)
#pragma unroll
        for (int k = 0; k < 8; ++k) {
            int j = tid + k * 256;
            const float4* Kr = (const float4*)(KbhH + (long)j * DHh);
            float dot = 0.0f;
#pragma unroll 4
            for (int d4 = 0; d4 < 16; ++d4) {
                float4 kv = Kr[d4];
                float4 qv = *(const float4*)(&s_q[h][d4 * 4]);
                dot += qv.x * kv.x + qv.y * kv.y + qv.z * kv.z + qv.w * kv.w;
            }
            s_zrow[j] = dot;
        }
        __syncthreads();

        // 2) Michelot: warp-redundant (identical trajectories), barrier-free
        float tau = dec_f(rmaxU[bhrowH]) - 1.02f;
        for (int it = 0; it < 48; ++it) {
            float s = 0.0f; int c = 0;
#pragma unroll 8
            for (int k = 0; k < 64; ++k) {
                float zz = s_zrow[lane + k * 32];
                if (zz > tau) { s += zz; c++; }
            }
#pragma unroll
            for (int off = 16; off; off >>= 1) {
                s += __shfl_xor_sync(0xffffffffu, s, off);
                c += __shfl_xor_sync(0xffffffffu, c, off);
            }
            float nt2 = (s - 1.0f) / (float)c;
            if (nt2 == tau) break;
            tau = nt2;
        }
        if (tid == 0) s_tau[h] = tau;

        // 3) heads: warp w covers keys [w*256,(w+1)*256); fixed-order combine
        {
            float o0 = 0.0f, o1 = 0.0f;
            for (int j = w * 256; j < w * 256 + 256; ++j) {
                float p = s_zrow[j] - tau;
                if (p > 0.0f) {
                    const float* Vr = Vb + (long)j * DHh;
                    o0 += p * Vr[lane];
                    o1 += p * Vr[lane + 32];
                }
            }
            s_hp0[w][lane] = o0;
            s_hp1[w][lane] = o1;
        }
        __syncthreads();
        if (tid < 32) {
            float o = 0.0f;
#pragma unroll
            for (int k = 0; k < 8; ++k) o += s_hp0[k][tid];
            heads[(long)row * Dd + h * DHh + tid] = o;
        } else if (tid < 64) {
            int d = tid - 32;
            float o = 0.0f;
#pragma unroll
            for (int k = 0; k < 8; ++k) o += s_hp1[k][d];
            heads[(long)row * Dd + h * DHh + 32 + d] = o;
        }

        // 4) avg contribution (unique writer per address)
#pragma unroll
        for (int k = 0; k < 8; ++k) {
            int j = tid + k * 256;
            float p = s_zrow[j] - tau;
            if (p > 0.0f) s_avg[j] += p;
        }
        __syncthreads();   // s_zrow/s_hp free for next overflow head
    }

    long abase = ((long)b * Ss + i) * (long)Ss;
#pragma unroll
    for (int k = 0; k < 8; ++k)
        avg_out[abase + tid + k * 256] = 0.125f * s_avg[tid + k * 256];
}

// ---------------------------------------------------------------------------
extern "C" void kernel_launch(void* const* d_in, const int* in_sizes, int n_in,
                              void* d_out, int out_size)
{
    const float* x    = (const float*)d_in[0];
    const float* Wq   = (const float*)d_in[1];
    const float* bq   = (const float*)d_in[2];
    const float* Wk   = (const float*)d_in[3];
    const float* bk   = (const float*)d_in[4];
    const float* Wv   = (const float*)d_in[5];
    const float* bv   = (const float*)d_in[6];
    const float* Wout = (const float*)d_in[7];
    const float* bout = (const float*)d_in[8];

    float* out   = (float*)d_out;
    float* x_out = out;                              // [B,S,D]
    float* avg   = out + (long)Bb * Ss * Dd;         // [B,S,S]

    float *Qp, *Kp, *Vp, *Hp;
    unsigned* Rp;
    unsigned short* Cp;
    int* Np;
    cudaGetSymbolAddress((void**)&Qp, g_Q);
    cudaGetSymbolAddress((void**)&Kp, g_K);
    cudaGetSymbolAddress((void**)&Vp, g_V);
    cudaGetSymbolAddress((void**)&Hp, g_heads);
    cudaGetSymbolAddress((void**)&Cp, g_cand);
    cudaGetSymbolAddress((void**)&Np, g_ccnt);
    cudaGetSymbolAddress((void**)&Rp, g_rmaxU);

    cudaFuncSetAttribute(qk_rowmax,
                         cudaFuncAttributeMaxDynamicSharedMemorySize, RMX_SMEM);
    cudaFuncSetAttribute(qk_screen2,
                         cudaFuncAttributeMaxDynamicSharedMemorySize, SCR_SMEM);
    cudaFuncSetAttribute(proj3t,
                         cudaFuncAttributeMaxDynamicSharedMemorySize, G3_SMEM);
    cudaFuncSetAttribute(wout3t,
                         cudaFuncAttributeMaxDynamicSharedMemorySize, G3_SMEM);

    // rowmax init: encoded 0 < enc(any finite float)
    cudaMemsetAsync(Rp, 0, Bb * Hh * Ss * sizeof(unsigned));

    // fused Q/K/V projections (3xtf32 tensor cores)
    proj3t<<<dim3(32, 17, 1), 256, G3_SMEM>>>(
        x, Wq, bq, Wk, bk, Wv, bv, Qp, Kp, Vp);

    // exact-threshold screening, K-half parallel
    qk_rowmax<<<dim3(2, 16, Bb * Hh), 256, RMX_SMEM>>>(Qp, Kp, Rp);
    qk_screen2<<<dim3(2, 16, Bb * Hh), 256, SCR_SMEM>>>(Qp, Kp, Rp, Cp, Np);

    // exact sparsemax + heads + avg from candidate lists
    sparse_final<<<Bb * Ss, 256>>>(Cp, Np, Rp, Qp, Kp, Vp, Hp, avg);

    // x_out = heads @ Wout + bout (3xtf32 tensor cores)
    wout3t<<<dim3(32, 8, 1), 256, G3_SMEM>>>(Hp, Wout, bout, x_out);
}

// round 17
// speedup vs baseline: 1.4886x; 1.1802x over previous
#include <cuda_runtime.h>

#define Bb 2
#define Ss 2048
#define Dd 512
#define Hh 8
#define DHh 64
#define CAPS 512     // total candidate cap per row (four 128-entry quarters)
#define QCAP 128     // per-quarter cap

// Scratch (device globals: no runtime allocation allowed)
__device__ float          g_Q[Bb * Hh * Ss * DHh];       // [B,H,S,dh]  8 MB
__device__ float          g_K[Bb * Hh * Ss * DHh];       // [B,H,S,dh]  8 MB
__device__ float          g_V[Bb * Ss * DHh];            // [B,S,dh]    1 MB
__device__ float          g_heads[Bb * Ss * Dd];         // [B,S,D]     8 MB
__device__ unsigned short g_cand[Bb * Hh * Ss * CAPS];   // cand indices 32 MB
__device__ int            g_ccnt[Bb * Hh * Ss * 4];      // per-quarter counts
__device__ unsigned       g_rmaxU[Bb * Hh * Ss];         // encoded row maxes

__device__ __forceinline__ unsigned enc_f(float f) {
    unsigned b = __float_as_uint(f);
    return (f >= 0.0f) ? (b | 0x80000000u) : ~b;
}
__device__ __forceinline__ float dec_f(unsigned u) {
    return (u & 0x80000000u) ? __uint_as_float(u & 0x7fffffffu)
                             : __uint_as_float(~u);
}
__device__ __forceinline__ unsigned f2tf32(float f) {
    unsigned u;
    asm("cvt.rna.tf32.f32 %0, %1;" : "=r"(u) : "f"(f));
    return u;
}

#define MMA3(d, a, b) asm volatile( \
    "mma.sync.aligned.m16n8k8.row.col.f32.tf32.tf32.f32 " \
    "{%0,%1,%2,%3}, {%4,%5,%6,%7}, {%8,%9}, {%0,%1,%2,%3};" \
    : "+f"(d[0]), "+f"(d[1]), "+f"(d[2]), "+f"(d[3]) \
    : "r"(a[0]), "r"(a[1]), "r"(a[2]), "r"(a[3]), "r"(b[0]), "r"(b[1]))

// ---------------------------------------------------------------------------
// 3xTF32 GEMM core (validated R11): C[128x64] = A(MxK)@W(KxN)+bias, K=512
// ---------------------------------------------------------------------------
#define G3_SMEM ((2 * 128 * 36 + 2 * 64 * 36) * 4)   // 55296 B

__device__ __forceinline__ void gemm3t_tile(
    const float* __restrict__ A, int lda,
    const float* __restrict__ W, int ldw,
    const float* __restrict__ bias,
    float* __restrict__ C,
    int m0, int n0, int ldc, int headMajor,
    unsigned* Ah, unsigned* Al, unsigned* Bh, unsigned* Bl)
{
    int tid = threadIdx.x;
    int wid = tid >> 5, lane = tid & 31;
    int wm = wid & 3, wn = wid >> 2;
    int g = lane >> 2, tg = lane & 3;

    float acc[2][4][4];
#pragma unroll
    for (int mt = 0; mt < 2; ++mt)
#pragma unroll
        for (int nt = 0; nt < 4; ++nt)
#pragma unroll
            for (int e = 0; e < 4; ++e) acc[mt][nt][e] = 0.0f;

    int arow = tid >> 1;
    int acb = (tid & 1) * 16;
    int bn = tid & 63;
    int bkb = (tid >> 6) * 8;

    for (int k0 = 0; k0 < Dd; k0 += 32) {
#pragma unroll
        for (int p = 0; p < 4; ++p) {
            int c = acb + p * 4;
            float4 v = *(const float4*)(A + (long)(m0 + arow) * lda + k0 + c);
            float vv[4] = {v.x, v.y, v.z, v.w};
#pragma unroll
            for (int u = 0; u < 4; ++u) {
                unsigned hi = f2tf32(vv[u]);
                Ah[arow * 36 + c + u] = hi;
                Al[arow * 36 + c + u] = f2tf32(vv[u] - __uint_as_float(hi));
            }
        }
#pragma unroll
        for (int u = 0; u < 8; ++u) {
            float v = W[(long)(k0 + bkb + u) * ldw + n0 + bn];
            unsigned hi = f2tf32(v);
            Bh[bn * 36 + bkb + u] = hi;
            Bl[bn * 36 + bkb + u] = f2tf32(v - __uint_as_float(hi));
        }
        __syncthreads();

#pragma unroll
        for (int kc = 0; kc < 32; kc += 8) {
            unsigned ah[2][4], al[2][4], bh[4][2], bl[4][2];
#pragma unroll
            for (int mt = 0; mt < 2; ++mt) {
                int r = wm * 32 + mt * 16 + g;
                ah[mt][0] = Ah[r * 36 + kc + tg];
                ah[mt][1] = Ah[(r + 8) * 36 + kc + tg];
                ah[mt][2] = Ah[r * 36 + kc + tg + 4];
                ah[mt][3] = Ah[(r + 8) * 36 + kc + tg + 4];
                al[mt][0] = Al[r * 36 + kc + tg];
                al[mt][1] = Al[(r + 8) * 36 + kc + tg];
                al[mt][2] = Al[r * 36 + kc + tg + 4];
                al[mt][3] = Al[(r + 8) * 36 + kc + tg + 4];
            }
#pragma unroll
            for (int nt = 0; nt < 4; ++nt) {
                int n = wn * 32 + nt * 8 + g;
                bh[nt][0] = Bh[n * 36 + kc + tg];
                bh[nt][1] = Bh[n * 36 + kc + tg + 4];
                bl[nt][0] = Bl[n * 36 + kc + tg];
                bl[nt][1] = Bl[n * 36 + kc + tg + 4];
            }
#pragma unroll
            for (int mt = 0; mt < 2; ++mt)
#pragma unroll
                for (int nt = 0; nt < 4; ++nt) {
                    MMA3(acc[mt][nt], ah[mt], bl[nt]);
                    MMA3(acc[mt][nt], al[mt], bh[nt]);
                    MMA3(acc[mt][nt], ah[mt], bh[nt]);
                }
        }
        __syncthreads();
    }

    int cb = wn * 32 + tg * 2;
#pragma unroll
    for (int mt = 0; mt < 2; ++mt) {
#pragma unroll
        for (int nt = 0; nt < 4; ++nt) {
            int r0 = m0 + wm * 32 + mt * 16 + g;
            int c = cb + nt * 8;
            float2 b2 = *(const float2*)(bias + n0 + c);
            float o0 = acc[mt][nt][0] + b2.x;
            float o1 = acc[mt][nt][1] + b2.y;
            float o2 = acc[mt][nt][2] + b2.x;
            float o3 = acc[mt][nt][3] + b2.y;
            if (headMajor) {
                int hh = n0 >> 6;
                int bb0 = r0 >> 11, ss0 = r0 & 2047;
                *(float2*)(C + ((((long)bb0 * Hh + hh) * Ss) + ss0) * DHh + c) =
                    make_float2(o0, o1);
                int r1 = r0 + 8;
                int bb1 = r1 >> 11, ss1 = r1 & 2047;
                *(float2*)(C + ((((long)bb1 * Hh + hh) * Ss) + ss1) * DHh + c) =
                    make_float2(o2, o3);
            } else {
                *(float2*)(C + (long)r0 * ldc + n0 + c) = make_float2(o0, o1);
                *(float2*)(C + (long)(r0 + 8) * ldc + n0 + c) = make_float2(o2, o3);
            }
        }
    }
}

__global__ __launch_bounds__(256) void proj3t(
    const float* __restrict__ x,
    const float* __restrict__ Wq, const float* __restrict__ bq,
    const float* __restrict__ Wk, const float* __restrict__ bk,
    const float* __restrict__ Wv, const float* __restrict__ bv,
    float* __restrict__ Qo, float* __restrict__ Ko, float* __restrict__ Vo)
{
    extern __shared__ unsigned sm3[];
    unsigned* Ah = sm3;
    unsigned* Al = sm3 + 128 * 36;
    unsigned* Bh = sm3 + 2 * 128 * 36;
    unsigned* Bl = Bh + 64 * 36;

    int y = blockIdx.y;
    int m0 = blockIdx.x * 128;
    if (y < 8)
        gemm3t_tile(x, Dd, Wq, Dd, bq, Qo, m0, y * 64, 0, 1, Ah, Al, Bh, Bl);
    else if (y < 16)
        gemm3t_tile(x, Dd, Wk, Dd, bk, Ko, m0, (y - 8) * 64, 0, 1, Ah, Al, Bh, Bl);
    else
        gemm3t_tile(x, Dd, Wv, DHh, bv, Vo, m0, 0, DHh, 0, Ah, Al, Bh, Bl);
}

__global__ __launch_bounds__(256) void wout3t(
    const float* __restrict__ A, const float* __restrict__ W,
    const float* __restrict__ bias, float* __restrict__ C)
{
    extern __shared__ unsigned sm3[];
    unsigned* Ah = sm3;
    unsigned* Al = sm3 + 128 * 36;
    unsigned* Bh = sm3 + 2 * 128 * 36;
    unsigned* Bl = Bh + 64 * 36;
    gemm3t_tile(A, Dd, W, Dd, bias, C,
                blockIdx.x * 128, blockIdx.y * 64, Dd, 0, Ah, Al, Bh, Bl);
}

// ---------------------------------------------------------------------------
// QK screening, K-half parallel (grid 2 x 16 x 16 = 512 CTAs per kernel).
// v2: row ownership fully factored -> register-resident counters/thresholds,
// no shared counters, no append phases, no smem atomics.
// ---------------------------------------------------------------------------
#define QK_LDS 68
#define QK_SMEM (2 * 128 * QK_LDS * 4)

__device__ __forceinline__ void tile_mma(
    const unsigned* Qs, const unsigned* Ks,
    int wm, int wn, int g, int tg, float acc[2][8][4])
{
#pragma unroll
    for (int mt = 0; mt < 2; ++mt)
#pragma unroll
        for (int nt = 0; nt < 8; ++nt)
#pragma unroll
            for (int e = 0; e < 4; ++e) acc[mt][nt][e] = 0.0f;

#pragma unroll
    for (int ks = 0; ks < 8; ++ks) {
        int kc = ks * 8;
        unsigned a[2][4];
#pragma unroll
        for (int mt = 0; mt < 2; ++mt) {
            int r = wm * 32 + mt * 16 + g;
            a[mt][0] = Qs[(r) * QK_LDS + kc + tg];
            a[mt][1] = Qs[(r + 8) * QK_LDS + kc + tg];
            a[mt][2] = Qs[(r) * QK_LDS + kc + tg + 4];
            a[mt][3] = Qs[(r + 8) * QK_LDS + kc + tg + 4];
        }
        unsigned b[8][2];
#pragma unroll
        for (int nt = 0; nt < 8; ++nt) {
            int n = wn * 64 + nt * 8 + g;
            b[nt][0] = Ks[n * QK_LDS + kc + tg];
            b[nt][1] = Ks[n * QK_LDS + kc + tg + 4];
        }
#pragma unroll
        for (int mt = 0; mt < 2; ++mt)
#pragma unroll
            for (int nt = 0; nt < 8; ++nt) {
                asm volatile(
                    "mma.sync.aligned.m16n8k8.row.col.f32.tf32.tf32.f32 "
                    "{%0,%1,%2,%3}, {%4,%5,%6,%7}, {%8,%9}, {%0,%1,%2,%3};"
                    : "+f"(acc[mt][nt][0]), "+f"(acc[mt][nt][1]),
                      "+f"(acc[mt][nt][2]), "+f"(acc[mt][nt][3])
                    : "r"(a[mt][0]), "r"(a[mt][1]), "r"(a[mt][2]), "r"(a[mt][3]),
                      "r"(b[nt][0]), "r"(b[nt][1]));
            }
    }
}

__device__ __forceinline__ void stage_qk(
    const float* __restrict__ G, unsigned* S, int tid)
{
#pragma unroll
    for (int p = 0; p < 8; ++p) {
        int r = (tid >> 4) + p * 16;
        int c = (tid & 15) * 4;
        float4 v = *(const float4*)(G + r * DHh + c);
        unsigned* s = S + r * QK_LDS + c;
        s[0] = f2tf32(v.x); s[1] = f2tf32(v.y);
        s[2] = f2tf32(v.z); s[3] = f2tf32(v.w);
    }
}

__global__ __launch_bounds__(256) void qk_rowmax(
    const float* __restrict__ Q, const float* __restrict__ K,
    unsigned* __restrict__ rmaxU)
{
    extern __shared__ unsigned sm[];
    unsigned* Qs = sm;
    unsigned* Ks = sm + 128 * QK_LDS;

    int tid = threadIdx.x;
    int wid = tid >> 5, lane = tid & 31;
    int wm = wid & 3, wn = wid >> 2;
    int g = lane >> 2, tg = lane & 3;

    int khalf = blockIdx.x;
    int q0 = blockIdx.y * 128;
    int bh = blockIdx.z;

    stage_qk(Q + ((long)bh * Ss + q0) * DHh, Qs, tid);
    __syncthreads();

    // running maxima for this quad's 4 rows (u = mt*2+hf -> row wm*32+u*8+g)
    float rm[4] = {-3e38f, -3e38f, -3e38f, -3e38f};

    float acc[2][8][4];
    for (int t = khalf * 8; t < khalf * 8 + 8; ++t) {
        stage_qk(K + ((long)bh * Ss + t * 128) * DHh, Ks, tid);
        __syncthreads();

        tile_mma(Qs, Ks, wm, wn, g, tg, acc);

#pragma unroll
        for (int mt = 0; mt < 2; ++mt) {
            float m0 = -3e38f, m1 = -3e38f;
#pragma unroll
            for (int nt = 0; nt < 8; ++nt) {
                m0 = fmaxf(m0, fmaxf(acc[mt][nt][0], acc[mt][nt][1]));
                m1 = fmaxf(m1, fmaxf(acc[mt][nt][2], acc[mt][nt][3]));
            }
            rm[mt * 2 + 0] = fmaxf(rm[mt * 2 + 0], m0);
            rm[mt * 2 + 1] = fmaxf(rm[mt * 2 + 1], m1);
        }
        __syncthreads();   // Ks reuse next tile
    }

    // quad reduce + one global atomicMax per row (single quad owner)
#pragma unroll
    for (int u = 0; u < 4; ++u) {
#pragma unroll
        for (int off = 1; off <= 2; off <<= 1)
            rm[u] = fmaxf(rm[u], __shfl_xor_sync(0xffffffffu, rm[u], off));
    }
    if (tg == 0) {
        long rowg0 = (long)bh * Ss + q0;
#pragma unroll
        for (int u = 0; u < 4; ++u)
            atomicMax(&rmaxU[rowg0 + wm * 32 + u * 8 + g], enc_f(rm[u]));
    }
}

__global__ __launch_bounds__(256) void qk_screen2(
    const float* __restrict__ Q, const float* __restrict__ K,
    const unsigned* __restrict__ rmaxU,
    unsigned short* __restrict__ cand, int* __restrict__ ccnt)
{
    extern __shared__ unsigned sm[];
    unsigned* Qs = sm;
    unsigned* Ks = sm + 128 * QK_LDS;

    int tid = threadIdx.x;
    int wid = tid >> 5, lane = tid & 31;
    int wm = wid & 3, wn = wid >> 2;
    int g = lane >> 2, tg = lane & 3;
    int qb = lane & ~3;

    int khalf = blockIdx.x;
    int q0 = blockIdx.y * 128;
    int bh = blockIdx.z;
    long rowg0 = (long)bh * Ss + q0;
    int quarter = khalf * 2 + wn;

    // register-resident thresholds + counters for this quad's 4 rows
    float thr[4];
    int cnt[4] = {0, 0, 0, 0};
#pragma unroll
    for (int u = 0; u < 4; ++u)
        thr[u] = dec_f(rmaxU[rowg0 + wm * 32 + u * 8 + g]) - 1.02f;

    stage_qk(Q + ((long)bh * Ss + q0) * DHh, Qs, tid);
    __syncthreads();

    float acc[2][8][4];
    for (int t = khalf * 8; t < khalf * 8 + 8; ++t) {
        stage_qk(K + ((long)bh * Ss + t * 128) * DHh, Ks, tid);
        __syncthreads();

        tile_mma(Qs, Ks, wm, wn, g, tg, acc);

        // phase-free append: this quad exclusively owns (row, quarter)
#pragma unroll
        for (int u = 0; u < 4; ++u) {
            int mt = u >> 1, hf = u & 1;
            unsigned m = 0;
#pragma unroll
            for (int nt = 0; nt < 8; ++nt) {
#pragma unroll
                for (int ee = 0; ee < 2; ++ee)
                    if (acc[mt][nt][hf * 2 + ee] > thr[u])
                        m |= 1u << (nt * 2 + ee);
            }
            int c = __popc(m);
            int c0 = __shfl_sync(0xffffffffu, c, qb);
            int c1 = __shfl_sync(0xffffffffu, c, qb + 1);
            int c2 = __shfl_sync(0xffffffffu, c, qb + 2);
            int c3 = __shfl_sync(0xffffffffu, c, qb + 3);
            int pre = (tg > 0 ? c0 : 0) + (tg > 1 ? c1 : 0) + (tg > 2 ? c2 : 0);
            int tot = c0 + c1 + c2 + c3;
            int pos = cnt[u] + pre;
            unsigned short* dst = cand +
                (rowg0 + wm * 32 + u * 8 + g) * (long)CAPS + quarter * QCAP;
            while (m) {
                int bit = __ffs(m) - 1; m &= m - 1;
                int j = t * 128 + wn * 64 + (bit >> 1) * 8 + tg * 2 + (bit & 1);
                if (pos < QCAP) dst[pos] = (unsigned short)j;
                ++pos;
            }
            cnt[u] += tot;
        }
        __syncthreads();   // Ks reuse next tile
    }

    if (tg == 0) {
#pragma unroll
        for (int u = 0; u < 4; ++u)
            ccnt[(rowg0 + wm * 32 + u * 8 + g) * 4 + quarter] = cnt[u];
    }
}

// ---------------------------------------------------------------------------
// Finish v4: 4-segment gather (CAPS=512), lane-parallel exact recompute,
// phased parallel avg, warp-redundant overflow Michelot. All deterministic.
// ---------------------------------------------------------------------------
__global__ __launch_bounds__(256, 4) void sparse_final(
    const unsigned short* __restrict__ cand, const int* __restrict__ ccnt,
    const unsigned* __restrict__ rmaxU,
    const float* __restrict__ Q, const float* __restrict__ K,
    const float* __restrict__ V,
    float* __restrict__ heads, float* __restrict__ avg_out)
{
    __shared__ float s_z[Hh][CAPS];
    __shared__ short s_j[Hh][CAPS];
    __shared__ __align__(16) float s_q[Hh][DHh];
    __shared__ float s_tau[Hh];
    __shared__ int   s_cnt[Hh];
    __shared__ int   s_over[Hh];
    __shared__ float s_avg[Ss];
    __shared__ float s_zrow[Ss];
    __shared__ float s_hp0[Hh][DHh / 2];
    __shared__ float s_hp1[Hh][DHh / 2];

    int row = blockIdx.x;
    int b = row >> 11;
    int i = row & 2047;
    int tid = threadIdx.x;
    int w = tid >> 5;
    int lane = tid & 31;

#pragma unroll
    for (int k = 0; k < 8; ++k) s_avg[tid + k * 256] = 0.0f;

    long bhrow = ((long)b * Hh + w) * Ss + i;
    const float* Qrow = Q + bhrow * DHh;
    const float* Kbh  = K + (((long)b * Hh + w) * Ss) * (long)DHh;
    const float* Vb   = V + (long)b * Ss * DHh;
    float q0 = Qrow[lane], q1 = Qrow[lane + 32];
    s_q[w][lane] = q0;
    s_q[w][lane + 32] = q1;
    float rmax = dec_f(rmaxU[bhrow]);

    int nq0 = ccnt[bhrow * 4 + 0];
    int nq1 = ccnt[bhrow * 4 + 1];
    int nq2 = ccnt[bhrow * 4 + 2];
    int nq3 = ccnt[bhrow * 4 + 3];
    bool over = (nq0 > QCAP) | (nq1 > QCAP) | (nq2 > QCAP) | (nq3 > QCAP);

    if (!over) {
        int n = nq0 + nq1 + nq2 + nq3;
        if (lane == 0) s_over[w] = 0;
        const unsigned short* cr = cand + bhrow * (long)CAPS;
        int off = 0;
        int nqs[4] = {nq0, nq1, nq2, nq3};
#pragma unroll
        for (int qq = 0; qq < 4; ++qq) {
            for (int e = lane; e < nqs[qq]; e += 32)
                s_j[w][off + e] = (short)cr[qq * QCAP + e];
            off += nqs[qq];
        }
        __syncwarp();

        // lane-parallel exact fp32 recompute (one candidate per lane)
        for (int e = lane; e < n; e += 32) {
            const float4* Kr = (const float4*)(Kbh + (long)s_j[w][e] * DHh);
            float dot = 0.0f;
#pragma unroll 4
            for (int d4 = 0; d4 < 16; ++d4) {
                float4 kv = Kr[d4];
                float4 qv = *(const float4*)(&s_q[w][d4 * 4]);
                dot += qv.x * kv.x + qv.y * kv.y + qv.z * kv.z + qv.w * kv.w;
            }
            s_z[w][e] = dot;
        }
        __syncwarp();

        // exact tau: Michelot over candidate superset
        float tau = rmax - 1.02f;
        for (int it = 0; it < 48; ++it) {
            float s = 0.0f; int c = 0;
            for (int e2 = lane; e2 < n; e2 += 32) {
                float zz = s_z[w][e2];
                if (zz > tau) { s += zz; c++; }
            }
#pragma unroll
            for (int off2 = 16; off2; off2 >>= 1) {
                s += __shfl_xor_sync(0xffffffffu, s, off2);
                c += __shfl_xor_sync(0xffffffffu, c, off2);
            }
            float nt2 = (s - 1.0f) / (float)c;
            if (nt2 == tau) break;
            tau = nt2;
        }
        if (lane == 0) { s_tau[w] = tau; s_cnt[w] = n; }

        // heads (p warp-uniform; only support contributes)
        float o0 = 0.0f, o1 = 0.0f;
        for (int e2 = 0; e2 < n; ++e2) {
            float p = s_z[w][e2] - tau;
            if (p > 0.0f) {
                const float* Vr = Vb + (long)s_j[w][e2] * DHh;
                o0 += p * Vr[lane];
                o1 += p * Vr[lane + 32];
            }
        }
        long hbase = (long)row * Dd + w * DHh;
        heads[hbase + lane] = o0;
        heads[hbase + lane + 32] = o1;
    } else {
        if (lane == 0) { s_over[w] = 1; s_cnt[w] = 0; s_tau[w] = 0.0f; }
    }

    __syncthreads();

    // avg accumulation, normal heads: per-head phase; within a phase all
    // candidate j distinct -> parallel += race-free.
#pragma unroll
    for (int h = 0; h < Hh; ++h) {
        int c = s_cnt[h];
        if (c > 0) {
            float th = s_tau[h];
            for (int e = tid; e < c; e += 256) {
                float p = s_z[h][e] - th;
                if (p > 0.0f) s_avg[s_j[h][e]] += p;
            }
        }
        __syncthreads();
    }

    // deferred overflow heads: block-parallel zrow, warp-redundant Michelot
    for (int h = 0; h < Hh; ++h) {
        if (!s_over[h]) continue;

        long bhrowH = ((long)b * Hh + h) * Ss + i;
        const float* KbhH = K + (((long)b * Hh + h) * Ss) * (long)DHh;

#pragma unroll
        for (int k = 0; k < 8; ++k) {
            int j = tid + k * 256;
            const float4* Kr = (const float4*)(KbhH + (long)j * DHh);
            float dot = 0.0f;
#pragma unroll 4
            for (int d4 = 0; d4 < 16; ++d4) {
                float4 kv = Kr[d4];
                float4 qv = *(const float4*)(&s_q[h][d4 * 4]);
                dot += qv.x * kv.x + qv.y * kv.y + qv.z * kv.z + qv.w * kv.w;
            }
            s_zrow[j] = dot;
        }
        __syncthreads();

        float tau = dec_f(rmaxU[bhrowH]) - 1.02f;
        for (int it = 0; it < 48; ++it) {
            float s = 0.0f; int c = 0;
#pragma unroll 8
            for (int k = 0; k < 64; ++k) {
                float zz = s_zrow[lane + k * 32];
                if (zz > tau) { s += zz; c++; }
            }
#pragma unroll
            for (int off2 = 16; off2; off2 >>= 1) {
                s += __shfl_xor_sync(0xffffffffu, s, off2);
                c += __shfl_xor_sync(0xffffffffu, c, off2);
            }
            float nt2 = (s - 1.0f) / (float)c;
            if (nt2 == tau) break;
            tau = nt2;
        }
        if (tid == 0) s_tau[h] = tau;

        {
            float o0 = 0.0f, o1 = 0.0f;
            for (int j = w * 256; j < w * 256 + 256; ++j) {
                float p = s_zrow[j] - tau;
                if (p > 0.0f) {
                    const float* Vr = Vb + (long)j * DHh;
                    o0 += p * Vr[lane];
                    o1 += p * Vr[lane + 32];
                }
            }
            s_hp0[w][lane] = o0;
            s_hp1[w][lane] = o1;
        }
        __syncthreads();
        if (tid < 32) {
            float o = 0.0f;
#pragma unroll
            for (int k = 0; k < 8; ++k) o += s_hp0[k][tid];
            heads[(long)row * Dd + h * DHh + tid] = o;
        } else if (tid < 64) {
            int d = tid - 32;
            float o = 0.0f;
#pragma unroll
            for (int k = 0; k < 8; ++k) o += s_hp1[k][d];
            heads[(long)row * Dd + h * DHh + 32 + d] = o;
        }

#pragma unroll
        for (int k = 0; k < 8; ++k) {
            int j = tid + k * 256;
            float p = s_zrow[j] - tau;
            if (p > 0.0f) s_avg[j] += p;
        }
        __syncthreads();
    }

    long abase = ((long)b * Ss + i) * (long)Ss;
#pragma unroll
    for (int k = 0; k < 8; ++k)
        avg_out[abase + tid + k * 256] = 0.125f * s_avg[tid + k * 256];
}

// ---------------------------------------------------------------------------
extern "C" void kernel_launch(void* const* d_in, const int* in_sizes, int n_in,
                              void* d_out, int out_size)
{
    const float* x    = (const float*)d_in[0];
    const float* Wq   = (const float*)d_in[1];
    const float* bq   = (const float*)d_in[2];
    const float* Wk   = (const float*)d_in[3];
    const float* bk   = (const float*)d_in[4];
    const float* Wv   = (const float*)d_in[5];
    const float* bv   = (const float*)d_in[6];
    const float* Wout = (const float*)d_in[7];
    const float* bout = (const float*)d_in[8];

    float* out   = (float*)d_out;
    float* x_out = out;                              // [B,S,D]
    float* avg   = out + (long)Bb * Ss * Dd;         // [B,S,S]

    float *Qp, *Kp, *Vp, *Hp;
    unsigned* Rp;
    unsigned short* Cp;
    int* Np;
    cudaGetSymbolAddress((void**)&Qp, g_Q);
    cudaGetSymbolAddress((void**)&Kp, g_K);
    cudaGetSymbolAddress((void**)&Vp, g_V);
    cudaGetSymbolAddress((void**)&Hp, g_heads);
    cudaGetSymbolAddress((void**)&Cp, g_cand);
    cudaGetSymbolAddress((void**)&Np, g_ccnt);
    cudaGetSymbolAddress((void**)&Rp, g_rmaxU);

    cudaFuncSetAttribute(qk_rowmax,
                         cudaFuncAttributeMaxDynamicSharedMemorySize, QK_SMEM);
    cudaFuncSetAttribute(qk_screen2,
                         cudaFuncAttributeMaxDynamicSharedMemorySize, QK_SMEM);
    cudaFuncSetAttribute(proj3t,
                         cudaFuncAttributeMaxDynamicSharedMemorySize, G3_SMEM);
    cudaFuncSetAttribute(wout3t,
                         cudaFuncAttributeMaxDynamicSharedMemorySize, G3_SMEM);

    // rowmax init: encoded 0 < enc(any finite float)
    cudaMemsetAsync(Rp, 0, Bb * Hh * Ss * sizeof(unsigned));

    // fused Q/K/V projections (3xtf32 tensor cores)
    proj3t<<<dim3(32, 17, 1), 256, G3_SMEM>>>(
        x, Wq, bq, Wk, bk, Wv, bv, Qp, Kp, Vp);

    // exact-threshold screening, K-half parallel
    qk_rowmax<<<dim3(2, 16, Bb * Hh), 256, QK_SMEM>>>(Qp, Kp, Rp);
    qk_screen2<<<dim3(2, 16, Bb * Hh), 256, QK_SMEM>>>(Qp, Kp, Rp, Cp, Np);

    // exact sparsemax + heads + avg from candidate lists
    sparse_final<<<Bb * Ss, 256>>>(Cp, Np, Rp, Qp, Kp, Vp, Hp, avg);

    // x_out = heads @ Wout + bout (3xtf32 tensor cores)
    wout3t<<<dim3(32, 8, 1), 256, G3_SMEM>>>(Hp, Wout, bout, x_out);
}